// round 14
// baseline (speedup 1.0000x reference)
#include <cuda_runtime.h>
#include <cuda_fp16.h>
#include <math.h>

#define NMAX   50000
#define EMAX   800000
#define HDIM   64
#define NHEADS 4
#define FIN    128
#define SCANB  256                       // elements per scan block

// ---------------- scratch (device globals; no allocation allowed) ----------
__device__ int      g_row[EMAX];
__device__ int      g_col[EMAX];
__device__ int      g_eoff[EMAX];        // edge's offset within its dst list
__device__ int      g_indeg[NMAX];
__device__ int      g_rowptr[NMAX + 1];
__device__ int      g_psum[(NMAX + SCANB - 1) / SCANB + 1];
__device__ int      g_psumex[(NMAX + SCANB - 1) / SCANB + 1];
__device__ int      g_csrc[EMAX];        // CSR: src node per in-edge, grouped by dst
__device__ float    g_dinv[NMAX];
__device__ __half   g_h1h [NMAX*HDIM];   // fp16: dinv[n] * (x @ W1)[n]
__device__ float    g_hA  [NMAX*HDIM];   // post-GCN (relu)
__device__ float    g_hg  [NMAX*NHEADS*HDIM]; // hA @ Wg, [n][h][c] fp32
__device__ half2    g_hgt [NMAX*HDIM*2]; // fp16 transposed copy [n][c][(h01),(h23)]
__device__ float    g_asrc[NMAX*NHEADS];
__device__ float    g_adst[NMAX*NHEADS];
__device__ float    g_hB  [NMAX*HDIM];   // post-GAT (relu), fp32
__device__ __half   g_hBh [NMAX*HDIM];   // post-GAT, fp16 copy for SAGE gather
__device__ float    g_macc[NMAX*HDIM];   // SAGE mean agg

__device__ __forceinline__ float lrelu02(float x) { return x >= 0.f ? x : 0.2f * x; }

__device__ __forceinline__ unsigned f2tf32(float f) {
    unsigned r;
    asm("cvt.rna.tf32.f32 %0, %1;" : "=r"(r) : "f"(f));
    return r;
}

// ---------------- convert + degree (saves per-edge offset) ------------------
__global__ void convert_deg_kernel(const void* __restrict__ eidx, int E) {
    int i = blockIdx.x * 256 + threadIdx.x;
    unsigned w = 0;
    if (i < E) w = ((const unsigned*)eidx)[2 * i + 1];
    int nz = __syncthreads_count(w != 0u);
    if (i >= E) return;
    int r, c;
    if (nz == 0) {  // int64 (odd words all zero)
        const long long* p = (const long long*)eidx;
        r = (int)p[i]; c = (int)p[i + E];
    } else {        // int32
        const int* p = (const int*)eidx;
        r = p[i]; c = p[i + E];
    }
    g_row[i] = r; g_col[i] = c;
    g_eoff[i] = atomicAdd(&g_indeg[c], 1);   // also the CSR slot index
}

// ---------------- parallel scan: phase 1 (block partial sums) ---------------
__global__ void scan_partial_kernel(int N) {
    __shared__ int sh[SCANB];
    int i = blockIdx.x * SCANB + threadIdx.x;
    int v = (i < N) ? g_indeg[i] : 0;
    sh[threadIdx.x] = v;
    __syncthreads();
    for (int off = SCANB / 2; off; off >>= 1) {
        if (threadIdx.x < off) sh[threadIdx.x] += sh[threadIdx.x + off];
        __syncthreads();
    }
    if (threadIdx.x == 0) g_psum[blockIdx.x] = sh[0];
}

// ---------------- phase 2: 1-block exclusive scan of partials ---------------
__global__ void scan_sum_kernel(int PB) {
    __shared__ int sh[SCANB];
    int tid = threadIdx.x;
    sh[tid] = (tid < PB) ? g_psum[tid] : 0;
    __syncthreads();
    for (int off = 1; off < SCANB; off <<= 1) {
        int v = (tid >= off) ? sh[tid - off] : 0;
        __syncthreads();
        sh[tid] += v;
        __syncthreads();
    }
    if (tid < PB) g_psumex[tid] = (tid > 0) ? sh[tid - 1] : 0;
    if (tid == 0) g_psumex[PB] = sh[SCANB - 1];
}

// ---------------- phase 3: expand (rowptr + dinv) ---------------------------
__global__ void scan_expand_kernel(int N) {
    __shared__ int sh[SCANB];
    int i = blockIdx.x * SCANB + threadIdx.x;
    int tid = threadIdx.x;
    int v = (i < N) ? g_indeg[i] : 0;
    sh[tid] = v;
    __syncthreads();
    for (int off = 1; off < SCANB; off <<= 1) {
        int a = (tid >= off) ? sh[tid - off] : 0;
        __syncthreads();
        sh[tid] += a;
        __syncthreads();
    }
    int base = g_psumex[blockIdx.x];
    if (i < N) {
        int excl = base + sh[tid] - v;
        g_rowptr[i] = excl;
        g_dinv[i] = rsqrtf((float)(v + 1));
        if (i == N - 1) g_rowptr[N] = excl + v;
    }
}

// ---------------- atomic-free CSR fill --------------------------------------
__global__ void fill_kernel(int E) {
    int i = blockIdx.x * blockDim.x + threadIdx.x;
    if (i >= E) return;
    g_csrc[g_rowptr[g_col[i]] + g_eoff[i]] = g_row[i];
}

// ===================== tf32 tensor-core GEMM ================================
#define KP(k8) (((k8) & 3) * 2 + ((k8) >> 2))

struct GemmSmem {
    unsigned As[128 * 36];   // [row][kstep*8 + kp], tf32 bits
    unsigned Wt[64 * 36];    // [col][kstep*8 + kp], tf32 bits
};

__device__ __forceinline__ void stage_A(GemmSmem* s, const float* __restrict__ A,
                                        int row0, int k0, int K, int M) {
    #pragma unroll
    for (int i = 0; i < 4; i++) {
        int idx = threadIdx.x + i * 256;
        int r = idx >> 3;
        int f4 = idx & 7;
        int gr = row0 + r;
        float4 v = (gr < M) ? *(const float4*)(A + (long)gr * K + k0 + f4 * 4)
                            : make_float4(0.f, 0.f, 0.f, 0.f);
        unsigned* dst = s->As + r * 36 + (f4 >> 1) * 8 + (f4 & 1);
        dst[0] = f2tf32(v.x);
        dst[2] = f2tf32(v.y);
        dst[4] = f2tf32(v.z);
        dst[6] = f2tf32(v.w);
    }
}

__device__ __forceinline__ void stage_W(GemmSmem* s, const float* __restrict__ W,
                                        int k0, int col0, int NC) {
    #pragma unroll
    for (int i = 0; i < 2; i++) {
        int idx = threadIdx.x + i * 256;
        int kl = idx >> 4;
        int f4 = idx & 15;
        float4 v = *(const float4*)(W + (long)(k0 + kl) * NC + col0 + f4 * 4);
        int kpos = (kl >> 3) * 8 + KP(kl & 7);
        s->Wt[(f4 * 4 + 0) * 36 + kpos] = f2tf32(v.x);
        s->Wt[(f4 * 4 + 1) * 36 + kpos] = f2tf32(v.y);
        s->Wt[(f4 * 4 + 2) * 36 + kpos] = f2tf32(v.z);
        s->Wt[(f4 * 4 + 3) * 36 + kpos] = f2tf32(v.w);
    }
}

__device__ __forceinline__ void mma_chunk(GemmSmem* s, int warp, int lane, float c[8][4]) {
    int g = lane >> 2, t = lane & 3;
    #pragma unroll
    for (int ks = 0; ks < 4; ks++) {
        unsigned a0, a1, a2, a3;
        {
            const unsigned* p1 = s->As + (warp * 16 + g) * 36 + ks * 8 + t * 2;
            const unsigned* p2 = p1 + 8 * 36;
            uint2 lo = *(const uint2*)p1;
            uint2 hi = *(const uint2*)p2;
            a0 = lo.x; a2 = lo.y; a1 = hi.x; a3 = hi.y;
        }
        #pragma unroll
        for (int nt = 0; nt < 8; nt++) {
            uint2 b = *(const uint2*)(s->Wt + (nt * 8 + g) * 36 + ks * 8 + t * 2);
            asm volatile(
                "mma.sync.aligned.m16n8k8.row.col.f32.tf32.tf32.f32 "
                "{%0,%1,%2,%3}, {%4,%5,%6,%7}, {%8,%9}, {%0,%1,%2,%3};"
                : "+f"(c[nt][0]), "+f"(c[nt][1]), "+f"(c[nt][2]), "+f"(c[nt][3])
                : "r"(a0), "r"(a1), "r"(a2), "r"(a3), "r"(b.x), "r"(b.y));
        }
    }
}

template<int K, bool BIAS, bool RELU>
__global__ __launch_bounds__(256) void gemm_tf32_kernel(
        const float* __restrict__ A, const float* __restrict__ W,
        const float* __restrict__ bias, float* __restrict__ out,
        int M, int NC) {
    __shared__ GemmSmem s;
    int row0 = blockIdx.x * 128;
    int col0 = blockIdx.y * 64;
    int warp = threadIdx.x >> 5, lane = threadIdx.x & 31;
    float c[8][4] = {};
    #pragma unroll
    for (int k0 = 0; k0 < K; k0 += 32) {
        stage_A(&s, A, row0, k0, K, M);
        stage_W(&s, W, k0, col0, NC);
        __syncthreads();
        mma_chunk(&s, warp, lane, c);
        __syncthreads();
    }
    int g = lane >> 2, t = lane & 3;
    int gr0 = row0 + warp * 16 + g;
    #pragma unroll
    for (int nt = 0; nt < 8; nt++) {
        int col = col0 + nt * 8 + t * 2;
        float bx = 0.f, by = 0.f;
        if (BIAS) { bx = bias[col]; by = bias[col + 1]; }
        float2 v0 = make_float2(c[nt][0] + bx, c[nt][1] + by);
        float2 v1 = make_float2(c[nt][2] + bx, c[nt][3] + by);
        if (RELU) {
            v0.x = fmaxf(v0.x, 0.f); v0.y = fmaxf(v0.y, 0.f);
            v1.x = fmaxf(v1.x, 0.f); v1.y = fmaxf(v1.y, 0.f);
        }
        if (gr0 < M)     *(float2*)(out + (long)gr0 * NC + col) = v0;
        if (gr0 + 8 < M) *(float2*)(out + (long)(gr0 + 8) * NC + col) = v1;
    }
}

// GCN GEMM variant: out fp16 = dinv[row] * (A@W)   (K=128, NC=64)
__global__ __launch_bounds__(256) void gemm_tf32_gcn_kernel(
        const float* __restrict__ A, const float* __restrict__ W,
        __half* __restrict__ out, int M) {
    __shared__ GemmSmem s;
    int row0 = blockIdx.x * 128;
    int warp = threadIdx.x >> 5, lane = threadIdx.x & 31;
    float c[8][4] = {};
    #pragma unroll
    for (int k0 = 0; k0 < FIN; k0 += 32) {
        stage_A(&s, A, row0, k0, FIN, M);
        stage_W(&s, W, k0, 0, HDIM);
        __syncthreads();
        mma_chunk(&s, warp, lane, c);
        __syncthreads();
    }
    int g = lane >> 2, t = lane & 3;
    int gr0 = row0 + warp * 16 + g;
    float dn0 = (gr0 < M) ? g_dinv[gr0] : 0.f;
    float dn1 = (gr0 + 8 < M) ? g_dinv[gr0 + 8] : 0.f;
    #pragma unroll
    for (int nt = 0; nt < 8; nt++) {
        int col = nt * 8 + t * 2;
        if (gr0 < M)
            *(half2*)(out + (long)gr0 * HDIM + col) =
                __floats2half2_rn(c[nt][0] * dn0, c[nt][1] * dn0);
        if (gr0 + 8 < M)
            *(half2*)(out + (long)(gr0 + 8) * HDIM + col) =
                __floats2half2_rn(c[nt][2] * dn1, c[nt][3] * dn1);
    }
}

// dual-pair tf32 GEMM: out = A1@W1v + A2@W2v + bias   (K = NC = 64)
__global__ __launch_bounds__(256) void gemm2_tf32_kernel(
        const float* __restrict__ A1, const float* __restrict__ W1v,
        const float* __restrict__ A2, const float* __restrict__ W2v,
        const float* __restrict__ bias, float* __restrict__ out, int M) {
    __shared__ GemmSmem s;
    int row0 = blockIdx.x * 128;
    int warp = threadIdx.x >> 5, lane = threadIdx.x & 31;
    float c[8][4] = {};
    #pragma unroll
    for (int p = 0; p < 2; p++) {
        const float* A = p ? A2 : A1;
        const float* W = p ? W2v : W1v;
        #pragma unroll
        for (int k0 = 0; k0 < 64; k0 += 32) {
            stage_A(&s, A, row0, k0, 64, M);
            stage_W(&s, W, k0, 0, 64);
            __syncthreads();
            mma_chunk(&s, warp, lane, c);
            __syncthreads();
        }
    }
    int g = lane >> 2, t = lane & 3;
    int gr0 = row0 + warp * 16 + g;
    #pragma unroll
    for (int nt = 0; nt < 8; nt++) {
        int col = nt * 8 + t * 2;
        float bx = bias[col], by = bias[col + 1];
        if (gr0 < M)
            *(float2*)(out + (long)gr0 * 64 + col) =
                make_float2(c[nt][0] + bx, c[nt][1] + by);
        if (gr0 + 8 < M)
            *(float2*)(out + (long)(gr0 + 8) * 64 + col) =
                make_float2(c[nt][2] + bx, c[nt][3] + by);
    }
}

// ---------------- GCN node gather (fp16 pre-scaled feed) --------------------
__global__ __launch_bounds__(64) void gcn_node_kernel(const float* __restrict__ b1) {
    int n = blockIdx.x;
    int c = threadIdx.x;
    int beg = g_rowptr[n], end = g_rowptr[n + 1];
    float acc0 = 0.f, acc1 = 0.f, acc2 = 0.f, acc3 = 0.f;
    int j = beg;
    for (; j + 4 <= end; j += 4) {
        int s0 = g_csrc[j], s1 = g_csrc[j + 1], s2 = g_csrc[j + 2], s3 = g_csrc[j + 3];
        acc0 += __half2float(g_h1h[s0 * HDIM + c]);
        acc1 += __half2float(g_h1h[s1 * HDIM + c]);
        acc2 += __half2float(g_h1h[s2 * HDIM + c]);
        acc3 += __half2float(g_h1h[s3 * HDIM + c]);
    }
    for (; j < end; j++) acc0 += __half2float(g_h1h[g_csrc[j] * HDIM + c]);
    float dn = g_dinv[n];
    float self = __half2float(g_h1h[n * HDIM + c]);
    float v = dn * (acc0 + acc1 + acc2 + acc3 + self) + b1[c];
    g_hA[n * HDIM + c] = fmaxf(v, 0.f);
}

// ---------------- GAT scores + fp16 transposed feature copy ----------------
__global__ void att_kernel(const float* __restrict__ att_src,
                           const float* __restrict__ att_dst, int N) {
    int warp = (blockIdx.x * blockDim.x + threadIdx.x) >> 5;
    int lane = threadIdx.x & 31;
    if (warp >= N) return;
    const float* hg = g_hg + (long)warp * (NHEADS * HDIM);
    float4 v1 = make_float4(hg[0 * HDIM + lane], hg[1 * HDIM + lane],
                            hg[2 * HDIM + lane], hg[3 * HDIM + lane]);
    float4 v2 = make_float4(hg[0 * HDIM + 32 + lane], hg[1 * HDIM + 32 + lane],
                            hg[2 * HDIM + 32 + lane], hg[3 * HDIM + 32 + lane]);
    {
        half2 a01 = __floats2half2_rn(v1.x, v1.y);
        half2 a23 = __floats2half2_rn(v1.z, v1.w);
        half2 b01 = __floats2half2_rn(v2.x, v2.y);
        half2 b23 = __floats2half2_rn(v2.z, v2.w);
        half2* dst1 = g_hgt + ((long)warp * HDIM + lane) * 2;
        half2* dst2 = g_hgt + ((long)warp * HDIM + lane + 32) * 2;
        dst1[0] = a01; dst1[1] = a23;
        dst2[0] = b01; dst2[1] = b23;
    }
    float s0, s1, s2, s3, d0, d1, d2, d3;
    s0 = v1.x * att_src[0 * HDIM + lane] + v2.x * att_src[0 * HDIM + lane + 32];
    s1 = v1.y * att_src[1 * HDIM + lane] + v2.y * att_src[1 * HDIM + lane + 32];
    s2 = v1.z * att_src[2 * HDIM + lane] + v2.z * att_src[2 * HDIM + lane + 32];
    s3 = v1.w * att_src[3 * HDIM + lane] + v2.w * att_src[3 * HDIM + lane + 32];
    d0 = v1.x * att_dst[0 * HDIM + lane] + v2.x * att_dst[0 * HDIM + lane + 32];
    d1 = v1.y * att_dst[1 * HDIM + lane] + v2.y * att_dst[1 * HDIM + lane + 32];
    d2 = v1.z * att_dst[2 * HDIM + lane] + v2.z * att_dst[2 * HDIM + lane + 32];
    d3 = v1.w * att_dst[3 * HDIM + lane] + v2.w * att_dst[3 * HDIM + lane + 32];
    #pragma unroll
    for (int o = 16; o; o >>= 1) {
        s0 += __shfl_xor_sync(0xffffffffu, s0, o);
        s1 += __shfl_xor_sync(0xffffffffu, s1, o);
        s2 += __shfl_xor_sync(0xffffffffu, s2, o);
        s3 += __shfl_xor_sync(0xffffffffu, s3, o);
        d0 += __shfl_xor_sync(0xffffffffu, d0, o);
        d1 += __shfl_xor_sync(0xffffffffu, d1, o);
        d2 += __shfl_xor_sync(0xffffffffu, d2, o);
        d3 += __shfl_xor_sync(0xffffffffu, d3, o);
    }
    if (lane == 0) {
        *(float4*)&g_asrc[warp * NHEADS] = make_float4(s0, s1, s2, s3);
        *(float4*)&g_adst[warp * NHEADS] = make_float4(d0, d1, d2, d3);
    }
}

// ---------------- GAT node: single fused sweep, 32-edge chunks --------------
__global__ __launch_bounds__(64) void gat_node_kernel(const float* __restrict__ bg) {
    __shared__ float s_alpha[32 * NHEADS];
    __shared__ int   s_src[32];
    __shared__ float s_denw[2 * NHEADS];

    int n = blockIdx.x;
    int tid = threadIdx.x;
    int lane = tid & 31, wid = tid >> 5;
    int beg = g_rowptr[n], end = g_rowptr[n + 1];

    float4 ad = *(const float4*)&g_adst[n * NHEADS];
    float4 asn = *(const float4*)&g_asrc[n * NHEADS];
    float ex_self[NHEADS] = {
        __expf(lrelu02(asn.x + ad.x)), __expf(lrelu02(asn.y + ad.y)),
        __expf(lrelu02(asn.z + ad.z)), __expf(lrelu02(asn.w + ad.w)) };

    int c = tid;
    float a0 = 0.f, a1 = 0.f, a2 = 0.f, a3 = 0.f;
    float dsum = 0.f;                    // head = tid&3 (64 and 0 offsets keep it)
    for (int base = beg; base < end; base += 32) {
        // stage 32 edges x 4 heads = 128 slots with 64 threads (2 each)
        #pragma unroll
        for (int halfp = 0; halfp < 2; halfp++) {
            int slot = tid + halfp * 64;     // 0..127; slot&3 == tid&3
            int jj = slot >> 2, h = slot & 3;
            int j = base + jj;
            float alpha = 0.f;
            int s = 0;
            if (j < end) {
                s = g_csrc[j];
                float av = g_asrc[s * NHEADS + h];
                float dv = ((const float*)&ad)[h];
                alpha = __expf(lrelu02(av + dv));
            }
            dsum += alpha;
            s_alpha[jj * NHEADS + h] = alpha;
            if (h == 0) s_src[jj] = s;
        }
        __syncthreads();
        #pragma unroll
        for (int jj = 0; jj < 32; jj++) {
            int s = s_src[jj];
            const uint2* hp = (const uint2*)(g_hgt + ((long)s * HDIM + c) * 2);
            uint2 raw = *hp;
            float2 f01 = __half22float2(*(half2*)&raw.x);
            float2 f23 = __half22float2(*(half2*)&raw.y);
            a0 += s_alpha[jj * NHEADS + 0] * f01.x;
            a1 += s_alpha[jj * NHEADS + 1] * f01.y;
            a2 += s_alpha[jj * NHEADS + 2] * f23.x;
            a3 += s_alpha[jj * NHEADS + 3] * f23.y;
        }
        __syncthreads();
    }
    dsum += __shfl_xor_sync(0xffffffffu, dsum, 4);
    dsum += __shfl_xor_sync(0xffffffffu, dsum, 8);
    dsum += __shfl_xor_sync(0xffffffffu, dsum, 16);
    if (lane < NHEADS) s_denw[wid * NHEADS + lane] = dsum;
    __syncthreads();

    {
        const float* hgp = g_hg + (long)n * (NHEADS * HDIM) + c;
        a0 += ex_self[0] * hgp[0];
        a1 += ex_self[1] * hgp[HDIM];
        a2 += ex_self[2] * hgp[2 * HDIM];
        a3 += ex_self[3] * hgp[3 * HDIM];
    }
    float den0 = s_denw[0] + s_denw[NHEADS + 0] + ex_self[0];
    float den1 = s_denw[1] + s_denw[NHEADS + 1] + ex_self[1];
    float den2 = s_denw[2] + s_denw[NHEADS + 2] + ex_self[2];
    float den3 = s_denw[3] + s_denw[NHEADS + 3] + ex_self[3];
    float acc = a0 / den0 + a1 / den1 + a2 / den2 + a3 / den3;
    float r = fmaxf(0.25f * acc + bg[c], 0.f);
    g_hB[n * HDIM + c] = r;
    g_hBh[n * HDIM + c] = __float2half(r);
}

// ---------------- SAGE node mean gather (fp16 feed) -------------------------
__global__ __launch_bounds__(64) void sage_node_kernel() {
    int n = blockIdx.x;
    int c = threadIdx.x;
    int beg = g_rowptr[n], end = g_rowptr[n + 1];
    float acc0 = 0.f, acc1 = 0.f, acc2 = 0.f, acc3 = 0.f;
    int j = beg;
    for (; j + 4 <= end; j += 4) {
        int s0 = g_csrc[j], s1 = g_csrc[j + 1], s2 = g_csrc[j + 2], s3 = g_csrc[j + 3];
        acc0 += __half2float(g_hBh[s0 * HDIM + c]);
        acc1 += __half2float(g_hBh[s1 * HDIM + c]);
        acc2 += __half2float(g_hBh[s2 * HDIM + c]);
        acc3 += __half2float(g_hBh[s3 * HDIM + c]);
    }
    for (; j < end; j++) acc0 += __half2float(g_hBh[g_csrc[j] * HDIM + c]);
    float inv = 1.f / fmaxf((float)(end - beg), 1.f);
    g_macc[n * HDIM + c] = (acc0 + acc1 + acc2 + acc3) * inv;
}

// ---------------- heads -----------------------------------------------------
__global__ void heads_kernel(const float* __restrict__ emb,
        const float* __restrict__ a1w, const float* __restrict__ a1b,
        const float* __restrict__ a2w, const float* __restrict__ a2b,
        const float* __restrict__ r1w, const float* __restrict__ r1b,
        const float* __restrict__ r2w, const float* __restrict__ r2b,
        float* __restrict__ anomaly, float* __restrict__ risk, int N) {
    int warp = (blockIdx.x * blockDim.x + threadIdx.x) >> 5;
    int lane = threadIdx.x & 31;
    if (warp >= N) return;
    const float* e = emb + (long)warp * HDIM;
    float sa = a1b[lane], sr = r1b[lane];
    #pragma unroll 8
    for (int k = 0; k < HDIM; k++) {
        float ev = e[k];
        sa += ev * a1w[k * 32 + lane];
        sr += ev * r1w[k * 32 + lane];
    }
    sa = fmaxf(sa, 0.f) * a2w[lane];
    sr = fmaxf(sr, 0.f) * r2w[lane];
    #pragma unroll
    for (int o = 16; o; o >>= 1) {
        sa += __shfl_xor_sync(0xffffffffu, sa, o);
        sr += __shfl_xor_sync(0xffffffffu, sr, o);
    }
    if (lane == 0) {
        anomaly[warp] = 1.f / (1.f + __expf(-(sa + a2b[0])));
        risk[warp]    = 1.f / (1.f + __expf(-(sr + r2b[0])));
    }
}

// ---------------- launch ----------------------------------------------------
extern "C" void kernel_launch(void* const* d_in, const int* in_sizes, int n_in,
                              void* d_out, int out_size) {
    const float* x    = (const float*)d_in[0];
    const void*  eidx = d_in[1];
    const float* W1   = (const float*)d_in[2];
    const float* b1   = (const float*)d_in[3];
    const float* Wg   = (const float*)d_in[4];
    const float *att_src, *att_dst, *bg;
    if (in_sizes[5] == NHEADS * HDIM) {        // dict order
        att_src = (const float*)d_in[5];
        att_dst = (const float*)d_in[6];
        bg      = (const float*)d_in[7];
    } else {                                    // signature order
        bg      = (const float*)d_in[5];
        att_src = (const float*)d_in[6];
        att_dst = (const float*)d_in[7];
    }
    const float* Wl  = (const float*)d_in[8];
    const float* bl  = (const float*)d_in[9];
    const float* Wr  = (const float*)d_in[10];
    const float* a1w = (const float*)d_in[11];
    const float* a1b = (const float*)d_in[12];
    const float* a2w = (const float*)d_in[13];
    const float* a2b = (const float*)d_in[14];
    const float* r1w = (const float*)d_in[15];
    const float* r1b = (const float*)d_in[16];
    const float* r2w = (const float*)d_in[17];
    const float* r2b = (const float*)d_in[18];

    int N = in_sizes[0] / FIN;
    int E = in_sizes[1] / 2;

    float* out_emb = (float*)d_out;
    float* out_an  = out_emb + (long)N * HDIM;
    float* out_rk  = out_an + N;

    void* p;
    cudaGetSymbolAddress(&p, g_indeg);  cudaMemsetAsync(p, 0, (size_t)N * 4);

    int PB = (N + SCANB - 1) / SCANB;

    convert_deg_kernel<<<(E + 255) / 256, 256>>>(eidx, E);
    scan_partial_kernel<<<PB, SCANB>>>(N);
    scan_sum_kernel<<<1, SCANB>>>(PB);
    scan_expand_kernel<<<PB, SCANB>>>(N);
    fill_kernel<<<(E + 255) / 256, 256>>>(E);

    int mtiles = (N + 127) / 128;

    // GCN:  h1h = fp16( dinv * (x @ W1) )
    {
        void* h1h; cudaGetSymbolAddress(&h1h, g_h1h);
        gemm_tf32_gcn_kernel<<<mtiles, 256>>>(x, W1, (__half*)h1h, N);
    }
    gcn_node_kernel<<<N, 64>>>(b1);

    // GAT:  hg = hA @ Wg  (K=64, NC=256 via 4 column blocks)
    {
        void* hA; cudaGetSymbolAddress(&hA, g_hA);
        void* hg; cudaGetSymbolAddress(&hg, g_hg);
        gemm_tf32_kernel<HDIM, false, false><<<dim3(mtiles, NHEADS), 256>>>(
            (const float*)hA, Wg, nullptr, (float*)hg, N, NHEADS * HDIM);
    }
    att_kernel<<<(N * 32 + 255) / 256, 256>>>(att_src, att_dst, N);
    gat_node_kernel<<<N, 64>>>(bg);

    // SAGE
    sage_node_kernel<<<N, 64>>>();
    {
        void* macc; cudaGetSymbolAddress(&macc, g_macc);
        void* hB;   cudaGetSymbolAddress(&hB, g_hB);
        gemm2_tf32_kernel<<<mtiles, 256>>>(
            (const float*)macc, Wl, (const float*)hB, Wr, bl, out_emb, N);
    }

    // heads
    heads_kernel<<<(N * 32 + 255) / 256, 256>>>(
        out_emb, a1w, a1b, a2w, a2b, r1w, r1b, r2w, r2b, out_an, out_rk, N);
}

// round 15
// speedup vs baseline: 1.0780x; 1.0780x over previous
#include <cuda_runtime.h>
#include <cuda_fp16.h>
#include <math.h>

#define NMAX   50000
#define EMAX   800000
#define HDIM   64
#define NHEADS 4
#define FIN    128
#define SCANB  256                       // elements per scan block

// ---------------- scratch (device globals; no allocation allowed) ----------
__device__ int      g_row[EMAX];
__device__ int      g_col[EMAX];
__device__ int      g_eoff[EMAX];        // edge's offset within its dst list
__device__ int      g_indeg[NMAX];
__device__ int      g_rowptr[NMAX + 1];
__device__ int      g_psum[(NMAX + SCANB - 1) / SCANB + 1];
__device__ int      g_psumex[(NMAX + SCANB - 1) / SCANB + 1];
__device__ int      g_csrc[EMAX];        // CSR: src node per in-edge, grouped by dst
__device__ float    g_dinv[NMAX];
__device__ __half   g_h1h [NMAX*HDIM];   // fp16: dinv[n] * (x @ W1)[n]
__device__ float    g_hA  [NMAX*HDIM];   // post-GCN (relu)
__device__ __half   g_hgh [NMAX*NHEADS*HDIM]; // hA @ Wg, fp16 [n][h][c]
__device__ half2    g_hgt [NMAX*HDIM*2]; // fp16 transposed copy [n][c][(h01),(h23)]
__device__ float    g_asrc[NMAX*NHEADS];
__device__ float    g_adst[NMAX*NHEADS];
__device__ float    g_hB  [NMAX*HDIM];   // post-GAT (relu), fp32
__device__ __half   g_hBh [NMAX*HDIM];   // post-GAT, fp16 copy for SAGE gather
__device__ float    g_macc[NMAX*HDIM];   // SAGE mean agg

__device__ __forceinline__ float lrelu02(float x) { return x >= 0.f ? x : 0.2f * x; }

__device__ __forceinline__ unsigned f2tf32(float f) {
    unsigned r;
    asm("cvt.rna.tf32.f32 %0, %1;" : "=r"(r) : "f"(f));
    return r;
}

// ---------------- convert + degree (saves per-edge offset) ------------------
__global__ void convert_deg_kernel(const void* __restrict__ eidx, int E) {
    int i = blockIdx.x * 256 + threadIdx.x;
    unsigned w = 0;
    if (i < E) w = ((const unsigned*)eidx)[2 * i + 1];
    int nz = __syncthreads_count(w != 0u);
    if (i >= E) return;
    int r, c;
    if (nz == 0) {  // int64 (odd words all zero)
        const long long* p = (const long long*)eidx;
        r = (int)p[i]; c = (int)p[i + E];
    } else {        // int32
        const int* p = (const int*)eidx;
        r = p[i]; c = p[i + E];
    }
    g_row[i] = r; g_col[i] = c;
    g_eoff[i] = atomicAdd(&g_indeg[c], 1);   // also the CSR slot index
}

// ---------------- parallel scan: phase 1 (block partial sums) ---------------
__global__ void scan_partial_kernel(int N) {
    __shared__ int sh[SCANB];
    int i = blockIdx.x * SCANB + threadIdx.x;
    int v = (i < N) ? g_indeg[i] : 0;
    sh[threadIdx.x] = v;
    __syncthreads();
    for (int off = SCANB / 2; off; off >>= 1) {
        if (threadIdx.x < off) sh[threadIdx.x] += sh[threadIdx.x + off];
        __syncthreads();
    }
    if (threadIdx.x == 0) g_psum[blockIdx.x] = sh[0];
}

// ---------------- phase 2: 1-block exclusive scan of partials ---------------
__global__ void scan_sum_kernel(int PB) {
    __shared__ int sh[SCANB];
    int tid = threadIdx.x;
    sh[tid] = (tid < PB) ? g_psum[tid] : 0;
    __syncthreads();
    for (int off = 1; off < SCANB; off <<= 1) {
        int v = (tid >= off) ? sh[tid - off] : 0;
        __syncthreads();
        sh[tid] += v;
        __syncthreads();
    }
    if (tid < PB) g_psumex[tid] = (tid > 0) ? sh[tid - 1] : 0;
    if (tid == 0) g_psumex[PB] = sh[SCANB - 1];
}

// ---------------- phase 3: expand (rowptr + dinv) ---------------------------
__global__ void scan_expand_kernel(int N) {
    __shared__ int sh[SCANB];
    int i = blockIdx.x * SCANB + threadIdx.x;
    int tid = threadIdx.x;
    int v = (i < N) ? g_indeg[i] : 0;
    sh[tid] = v;
    __syncthreads();
    for (int off = 1; off < SCANB; off <<= 1) {
        int a = (tid >= off) ? sh[tid - off] : 0;
        __syncthreads();
        sh[tid] += a;
        __syncthreads();
    }
    int base = g_psumex[blockIdx.x];
    if (i < N) {
        int excl = base + sh[tid] - v;
        g_rowptr[i] = excl;
        g_dinv[i] = rsqrtf((float)(v + 1));
        if (i == N - 1) g_rowptr[N] = excl + v;
    }
}

// ---------------- atomic-free CSR fill --------------------------------------
__global__ void fill_kernel(int E) {
    int i = blockIdx.x * blockDim.x + threadIdx.x;
    if (i >= E) return;
    g_csrc[g_rowptr[g_col[i]] + g_eoff[i]] = g_row[i];
}

// ===================== tf32 tensor-core GEMM ================================
#define KP(k8) (((k8) & 3) * 2 + ((k8) >> 2))

struct GemmSmem {
    unsigned As[128 * 36];   // [row][kstep*8 + kp], tf32 bits
    unsigned Wt[64 * 36];    // [col][kstep*8 + kp], tf32 bits
};

__device__ __forceinline__ void stage_A(GemmSmem* s, const float* __restrict__ A,
                                        int row0, int k0, int K, int M) {
    #pragma unroll
    for (int i = 0; i < 4; i++) {
        int idx = threadIdx.x + i * 256;
        int r = idx >> 3;
        int f4 = idx & 7;
        int gr = row0 + r;
        float4 v = (gr < M) ? *(const float4*)(A + (long)gr * K + k0 + f4 * 4)
                            : make_float4(0.f, 0.f, 0.f, 0.f);
        unsigned* dst = s->As + r * 36 + (f4 >> 1) * 8 + (f4 & 1);
        dst[0] = f2tf32(v.x);
        dst[2] = f2tf32(v.y);
        dst[4] = f2tf32(v.z);
        dst[6] = f2tf32(v.w);
    }
}

__device__ __forceinline__ void stage_W(GemmSmem* s, const float* __restrict__ W,
                                        int k0, int col0, int NC) {
    #pragma unroll
    for (int i = 0; i < 2; i++) {
        int idx = threadIdx.x + i * 256;
        int kl = idx >> 4;
        int f4 = idx & 15;
        float4 v = *(const float4*)(W + (long)(k0 + kl) * NC + col0 + f4 * 4);
        int kpos = (kl >> 3) * 8 + KP(kl & 7);
        s->Wt[(f4 * 4 + 0) * 36 + kpos] = f2tf32(v.x);
        s->Wt[(f4 * 4 + 1) * 36 + kpos] = f2tf32(v.y);
        s->Wt[(f4 * 4 + 2) * 36 + kpos] = f2tf32(v.z);
        s->Wt[(f4 * 4 + 3) * 36 + kpos] = f2tf32(v.w);
    }
}

__device__ __forceinline__ void mma_chunk(GemmSmem* s, int warp, int lane, float c[8][4]) {
    int g = lane >> 2, t = lane & 3;
    #pragma unroll
    for (int ks = 0; ks < 4; ks++) {
        unsigned a0, a1, a2, a3;
        {
            const unsigned* p1 = s->As + (warp * 16 + g) * 36 + ks * 8 + t * 2;
            const unsigned* p2 = p1 + 8 * 36;
            uint2 lo = *(const uint2*)p1;
            uint2 hi = *(const uint2*)p2;
            a0 = lo.x; a2 = lo.y; a1 = hi.x; a3 = hi.y;
        }
        #pragma unroll
        for (int nt = 0; nt < 8; nt++) {
            uint2 b = *(const uint2*)(s->Wt + (nt * 8 + g) * 36 + ks * 8 + t * 2);
            asm volatile(
                "mma.sync.aligned.m16n8k8.row.col.f32.tf32.tf32.f32 "
                "{%0,%1,%2,%3}, {%4,%5,%6,%7}, {%8,%9}, {%0,%1,%2,%3};"
                : "+f"(c[nt][0]), "+f"(c[nt][1]), "+f"(c[nt][2]), "+f"(c[nt][3])
                : "r"(a0), "r"(a1), "r"(a2), "r"(a3), "r"(b.x), "r"(b.y));
        }
    }
}

// GAT GEMM: hgh fp16[n][h][c] = hA @ Wg (head = blockIdx.y)
__global__ __launch_bounds__(256) void gemm_tf32_gat_kernel(
        const float* __restrict__ A, const float* __restrict__ W,
        __half* __restrict__ outh, int M) {
    __shared__ GemmSmem s;
    int row0 = blockIdx.x * 128;
    int col0 = blockIdx.y * 64;
    int warp = threadIdx.x >> 5, lane = threadIdx.x & 31;
    float c[8][4] = {};
    #pragma unroll
    for (int k0 = 0; k0 < HDIM; k0 += 32) {
        stage_A(&s, A, row0, k0, HDIM, M);
        stage_W(&s, W, k0, col0, NHEADS * HDIM);
        __syncthreads();
        mma_chunk(&s, warp, lane, c);
        __syncthreads();
    }
    int g = lane >> 2, t = lane & 3;
    int gr0 = row0 + warp * 16 + g;
    #pragma unroll
    for (int nt = 0; nt < 8; nt++) {
        int col = col0 + nt * 8 + t * 2;   // global col within 256
        if (gr0 < M)
            *(half2*)(outh + (long)gr0 * (NHEADS * HDIM) + col) =
                __floats2half2_rn(c[nt][0], c[nt][1]);
        if (gr0 + 8 < M)
            *(half2*)(outh + (long)(gr0 + 8) * (NHEADS * HDIM) + col) =
                __floats2half2_rn(c[nt][2], c[nt][3]);
    }
}

// GCN GEMM variant: out fp16 = dinv[row] * (A@W)   (K=128, NC=64)
__global__ __launch_bounds__(256) void gemm_tf32_gcn_kernel(
        const float* __restrict__ A, const float* __restrict__ W,
        __half* __restrict__ out, int M) {
    __shared__ GemmSmem s;
    int row0 = blockIdx.x * 128;
    int warp = threadIdx.x >> 5, lane = threadIdx.x & 31;
    float c[8][4] = {};
    #pragma unroll
    for (int k0 = 0; k0 < FIN; k0 += 32) {
        stage_A(&s, A, row0, k0, FIN, M);
        stage_W(&s, W, k0, 0, HDIM);
        __syncthreads();
        mma_chunk(&s, warp, lane, c);
        __syncthreads();
    }
    int g = lane >> 2, t = lane & 3;
    int gr0 = row0 + warp * 16 + g;
    float dn0 = (gr0 < M) ? g_dinv[gr0] : 0.f;
    float dn1 = (gr0 + 8 < M) ? g_dinv[gr0 + 8] : 0.f;
    #pragma unroll
    for (int nt = 0; nt < 8; nt++) {
        int col = nt * 8 + t * 2;
        if (gr0 < M)
            *(half2*)(out + (long)gr0 * HDIM + col) =
                __floats2half2_rn(c[nt][0] * dn0, c[nt][1] * dn0);
        if (gr0 + 8 < M)
            *(half2*)(out + (long)(gr0 + 8) * HDIM + col) =
                __floats2half2_rn(c[nt][2] * dn1, c[nt][3] * dn1);
    }
}

// dual-pair tf32 GEMM: out = A1@W1v + A2@W2v + bias   (K = NC = 64)
__global__ __launch_bounds__(256) void gemm2_tf32_kernel(
        const float* __restrict__ A1, const float* __restrict__ W1v,
        const float* __restrict__ A2, const float* __restrict__ W2v,
        const float* __restrict__ bias, float* __restrict__ out, int M) {
    __shared__ GemmSmem s;
    int row0 = blockIdx.x * 128;
    int warp = threadIdx.x >> 5, lane = threadIdx.x & 31;
    float c[8][4] = {};
    #pragma unroll
    for (int p = 0; p < 2; p++) {
        const float* A = p ? A2 : A1;
        const float* W = p ? W2v : W1v;
        #pragma unroll
        for (int k0 = 0; k0 < 64; k0 += 32) {
            stage_A(&s, A, row0, k0, 64, M);
            stage_W(&s, W, k0, 0, 64);
            __syncthreads();
            mma_chunk(&s, warp, lane, c);
            __syncthreads();
        }
    }
    int g = lane >> 2, t = lane & 3;
    int gr0 = row0 + warp * 16 + g;
    #pragma unroll
    for (int nt = 0; nt < 8; nt++) {
        int col = nt * 8 + t * 2;
        float bx = bias[col], by = bias[col + 1];
        if (gr0 < M)
            *(float2*)(out + (long)gr0 * 64 + col) =
                make_float2(c[nt][0] + bx, c[nt][1] + by);
        if (gr0 + 8 < M)
            *(float2*)(out + (long)(gr0 + 8) * 64 + col) =
                make_float2(c[nt][2] + bx, c[nt][3] + by);
    }
}

// ---------------- GCN node gather (fp16 pre-scaled feed) --------------------
__global__ __launch_bounds__(64) void gcn_node_kernel(const float* __restrict__ b1) {
    int n = blockIdx.x;
    int c = threadIdx.x;
    int beg = g_rowptr[n], end = g_rowptr[n + 1];
    float acc0 = 0.f, acc1 = 0.f, acc2 = 0.f, acc3 = 0.f;
    int j = beg;
    for (; j + 4 <= end; j += 4) {
        int s0 = g_csrc[j], s1 = g_csrc[j + 1], s2 = g_csrc[j + 2], s3 = g_csrc[j + 3];
        acc0 += __half2float(g_h1h[s0 * HDIM + c]);
        acc1 += __half2float(g_h1h[s1 * HDIM + c]);
        acc2 += __half2float(g_h1h[s2 * HDIM + c]);
        acc3 += __half2float(g_h1h[s3 * HDIM + c]);
    }
    for (; j < end; j++) acc0 += __half2float(g_h1h[g_csrc[j] * HDIM + c]);
    float dn = g_dinv[n];
    float self = __half2float(g_h1h[n * HDIM + c]);
    float v = dn * (acc0 + acc1 + acc2 + acc3 + self) + b1[c];
    g_hA[n * HDIM + c] = fmaxf(v, 0.f);
}

// ---------------- GAT scores + transposed repack (fp16 in, fp16 out) --------
__global__ void att_kernel(const float* __restrict__ att_src,
                           const float* __restrict__ att_dst, int N) {
    int warp = (blockIdx.x * blockDim.x + threadIdx.x) >> 5;
    int lane = threadIdx.x & 31;
    if (warp >= N) return;
    const half2* hg = (const half2*)(g_hgh + (long)warp * (NHEADS * HDIM));
    // lane covers cols 2*lane, 2*lane+1 for all 4 heads
    half2 v0 = hg[0 * 32 + lane];
    half2 v1 = hg[1 * 32 + lane];
    half2 v2 = hg[2 * 32 + lane];
    half2 v3 = hg[3 * 32 + lane];
    // transposed repack: [n][c][h] — one coalesced 16B store per lane
    {
        half2 p01 = __lows2half2(v0, v1);    // (h0,h1) at c=2*lane
        half2 p23 = __lows2half2(v2, v3);
        half2 q01 = __highs2half2(v0, v1);   // (h0,h1) at c=2*lane+1
        half2 q23 = __highs2half2(v2, v3);
        uint4 pk;
        pk.x = *(unsigned*)&p01; pk.y = *(unsigned*)&p23;
        pk.z = *(unsigned*)&q01; pk.w = *(unsigned*)&q23;
        *(uint4*)(g_hgt + ((long)warp * HDIM + 2 * lane) * 2) = pk;
    }
    float2 f0 = __half22float2(v0), f1 = __half22float2(v1);
    float2 f2 = __half22float2(v2), f3 = __half22float2(v3);
    int c2 = 2 * lane;
    float2 as0 = *(const float2*)&att_src[0 * HDIM + c2];
    float2 as1 = *(const float2*)&att_src[1 * HDIM + c2];
    float2 as2 = *(const float2*)&att_src[2 * HDIM + c2];
    float2 as3 = *(const float2*)&att_src[3 * HDIM + c2];
    float2 ad0 = *(const float2*)&att_dst[0 * HDIM + c2];
    float2 ad1 = *(const float2*)&att_dst[1 * HDIM + c2];
    float2 ad2 = *(const float2*)&att_dst[2 * HDIM + c2];
    float2 ad3 = *(const float2*)&att_dst[3 * HDIM + c2];
    float s0 = f0.x * as0.x + f0.y * as0.y;
    float s1 = f1.x * as1.x + f1.y * as1.y;
    float s2 = f2.x * as2.x + f2.y * as2.y;
    float s3 = f3.x * as3.x + f3.y * as3.y;
    float d0 = f0.x * ad0.x + f0.y * ad0.y;
    float d1 = f1.x * ad1.x + f1.y * ad1.y;
    float d2 = f2.x * ad2.x + f2.y * ad2.y;
    float d3 = f3.x * ad3.x + f3.y * ad3.y;
    #pragma unroll
    for (int o = 16; o; o >>= 1) {
        s0 += __shfl_xor_sync(0xffffffffu, s0, o);
        s1 += __shfl_xor_sync(0xffffffffu, s1, o);
        s2 += __shfl_xor_sync(0xffffffffu, s2, o);
        s3 += __shfl_xor_sync(0xffffffffu, s3, o);
        d0 += __shfl_xor_sync(0xffffffffu, d0, o);
        d1 += __shfl_xor_sync(0xffffffffu, d1, o);
        d2 += __shfl_xor_sync(0xffffffffu, d2, o);
        d3 += __shfl_xor_sync(0xffffffffu, d3, o);
    }
    if (lane == 0) {
        *(float4*)&g_asrc[warp * NHEADS] = make_float4(s0, s1, s2, s3);
        *(float4*)&g_adst[warp * NHEADS] = make_float4(d0, d1, d2, d3);
    }
}

// ---------------- GAT node: single fused sweep, 16-edge chunks --------------
__global__ __launch_bounds__(64) void gat_node_kernel(const float* __restrict__ bg) {
    __shared__ float s_alpha[16 * NHEADS];
    __shared__ int   s_src[16];
    __shared__ float s_denw[2 * NHEADS];

    int n = blockIdx.x;
    int tid = threadIdx.x;
    int lane = tid & 31, wid = tid >> 5;
    int beg = g_rowptr[n], end = g_rowptr[n + 1];

    float4 ad = *(const float4*)&g_adst[n * NHEADS];
    float4 asn = *(const float4*)&g_asrc[n * NHEADS];
    float ex_self[NHEADS] = {
        __expf(lrelu02(asn.x + ad.x)), __expf(lrelu02(asn.y + ad.y)),
        __expf(lrelu02(asn.z + ad.z)), __expf(lrelu02(asn.w + ad.w)) };

    int c = tid;
    float a0 = 0.f, a1 = 0.f, a2 = 0.f, a3 = 0.f;
    float dsum = 0.f;
    for (int base = beg; base < end; base += 16) {
        {
            int jj = tid >> 2, h = tid & 3;
            int j = base + jj;
            float alpha = 0.f;
            int s = 0;
            if (j < end) {
                s = g_csrc[j];
                float av = g_asrc[s * NHEADS + h];
                float dv = ((const float*)&ad)[h];
                alpha = __expf(lrelu02(av + dv));
            }
            dsum += alpha;
            s_alpha[jj * NHEADS + h] = alpha;
            if (h == 0) s_src[jj] = s;
        }
        __syncthreads();
        #pragma unroll
        for (int jj = 0; jj < 16; jj++) {
            int s = s_src[jj];
            const uint2* hp = (const uint2*)(g_hgt + ((long)s * HDIM + c) * 2);
            uint2 raw = *hp;
            float2 f01 = __half22float2(*(half2*)&raw.x);
            float2 f23 = __half22float2(*(half2*)&raw.y);
            a0 += s_alpha[jj * NHEADS + 0] * f01.x;
            a1 += s_alpha[jj * NHEADS + 1] * f01.y;
            a2 += s_alpha[jj * NHEADS + 2] * f23.x;
            a3 += s_alpha[jj * NHEADS + 3] * f23.y;
        }
        __syncthreads();
    }
    dsum += __shfl_xor_sync(0xffffffffu, dsum, 4);
    dsum += __shfl_xor_sync(0xffffffffu, dsum, 8);
    dsum += __shfl_xor_sync(0xffffffffu, dsum, 16);
    if (lane < NHEADS) s_denw[wid * NHEADS + lane] = dsum;
    __syncthreads();

    // self contribution from the fp16 transposed copy
    {
        uint2 raw = *(const uint2*)(g_hgt + ((long)n * HDIM + c) * 2);
        float2 f01 = __half22float2(*(half2*)&raw.x);
        float2 f23 = __half22float2(*(half2*)&raw.y);
        a0 += ex_self[0] * f01.x;
        a1 += ex_self[1] * f01.y;
        a2 += ex_self[2] * f23.x;
        a3 += ex_self[3] * f23.y;
    }
    float den0 = s_denw[0] + s_denw[NHEADS + 0] + ex_self[0];
    float den1 = s_denw[1] + s_denw[NHEADS + 1] + ex_self[1];
    float den2 = s_denw[2] + s_denw[NHEADS + 2] + ex_self[2];
    float den3 = s_denw[3] + s_denw[NHEADS + 3] + ex_self[3];
    float acc = a0 / den0 + a1 / den1 + a2 / den2 + a3 / den3;
    float r = fmaxf(0.25f * acc + bg[c], 0.f);
    g_hB[n * HDIM + c] = r;
    g_hBh[n * HDIM + c] = __float2half(r);
}

// ---------------- SAGE node mean gather (fp16 feed) -------------------------
__global__ __launch_bounds__(64) void sage_node_kernel() {
    int n = blockIdx.x;
    int c = threadIdx.x;
    int beg = g_rowptr[n], end = g_rowptr[n + 1];
    float acc0 = 0.f, acc1 = 0.f, acc2 = 0.f, acc3 = 0.f;
    int j = beg;
    for (; j + 4 <= end; j += 4) {
        int s0 = g_csrc[j], s1 = g_csrc[j + 1], s2 = g_csrc[j + 2], s3 = g_csrc[j + 3];
        acc0 += __half2float(g_hBh[s0 * HDIM + c]);
        acc1 += __half2float(g_hBh[s1 * HDIM + c]);
        acc2 += __half2float(g_hBh[s2 * HDIM + c]);
        acc3 += __half2float(g_hBh[s3 * HDIM + c]);
    }
    for (; j < end; j++) acc0 += __half2float(g_hBh[g_csrc[j] * HDIM + c]);
    float inv = 1.f / fmaxf((float)(end - beg), 1.f);
    g_macc[n * HDIM + c] = (acc0 + acc1 + acc2 + acc3) * inv;
}

// ---------------- heads -----------------------------------------------------
__global__ void heads_kernel(const float* __restrict__ emb,
        const float* __restrict__ a1w, const float* __restrict__ a1b,
        const float* __restrict__ a2w, const float* __restrict__ a2b,
        const float* __restrict__ r1w, const float* __restrict__ r1b,
        const float* __restrict__ r2w, const float* __restrict__ r2b,
        float* __restrict__ anomaly, float* __restrict__ risk, int N) {
    int warp = (blockIdx.x * blockDim.x + threadIdx.x) >> 5;
    int lane = threadIdx.x & 31;
    if (warp >= N) return;
    const float* e = emb + (long)warp * HDIM;
    float sa = a1b[lane], sr = r1b[lane];
    #pragma unroll 8
    for (int k = 0; k < HDIM; k++) {
        float ev = e[k];
        sa += ev * a1w[k * 32 + lane];
        sr += ev * r1w[k * 32 + lane];
    }
    sa = fmaxf(sa, 0.f) * a2w[lane];
    sr = fmaxf(sr, 0.f) * r2w[lane];
    #pragma unroll
    for (int o = 16; o; o >>= 1) {
        sa += __shfl_xor_sync(0xffffffffu, sa, o);
        sr += __shfl_xor_sync(0xffffffffu, sr, o);
    }
    if (lane == 0) {
        anomaly[warp] = 1.f / (1.f + __expf(-(sa + a2b[0])));
        risk[warp]    = 1.f / (1.f + __expf(-(sr + r2b[0])));
    }
}

// ---------------- launch ----------------------------------------------------
extern "C" void kernel_launch(void* const* d_in, const int* in_sizes, int n_in,
                              void* d_out, int out_size) {
    const float* x    = (const float*)d_in[0];
    const void*  eidx = d_in[1];
    const float* W1   = (const float*)d_in[2];
    const float* b1   = (const float*)d_in[3];
    const float* Wg   = (const float*)d_in[4];
    const float *att_src, *att_dst, *bg;
    if (in_sizes[5] == NHEADS * HDIM) {        // dict order
        att_src = (const float*)d_in[5];
        att_dst = (const float*)d_in[6];
        bg      = (const float*)d_in[7];
    } else {                                    // signature order
        bg      = (const float*)d_in[5];
        att_src = (const float*)d_in[6];
        att_dst = (const float*)d_in[7];
    }
    const float* Wl  = (const float*)d_in[8];
    const float* bl  = (const float*)d_in[9];
    const float* Wr  = (const float*)d_in[10];
    const float* a1w = (const float*)d_in[11];
    const float* a1b = (const float*)d_in[12];
    const float* a2w = (const float*)d_in[13];
    const float* a2b = (const float*)d_in[14];
    const float* r1w = (const float*)d_in[15];
    const float* r1b = (const float*)d_in[16];
    const float* r2w = (const float*)d_in[17];
    const float* r2b = (const float*)d_in[18];

    int N = in_sizes[0] / FIN;
    int E = in_sizes[1] / 2;

    float* out_emb = (float*)d_out;
    float* out_an  = out_emb + (long)N * HDIM;
    float* out_rk  = out_an + N;

    void* p;
    cudaGetSymbolAddress(&p, g_indeg);  cudaMemsetAsync(p, 0, (size_t)N * 4);

    int PB = (N + SCANB - 1) / SCANB;

    convert_deg_kernel<<<(E + 255) / 256, 256>>>(eidx, E);
    scan_partial_kernel<<<PB, SCANB>>>(N);
    scan_sum_kernel<<<1, SCANB>>>(PB);
    scan_expand_kernel<<<PB, SCANB>>>(N);
    fill_kernel<<<(E + 255) / 256, 256>>>(E);

    int mtiles = (N + 127) / 128;

    // GCN:  h1h = fp16( dinv * (x @ W1) )
    {
        void* h1h; cudaGetSymbolAddress(&h1h, g_h1h);
        gemm_tf32_gcn_kernel<<<mtiles, 256>>>(x, W1, (__half*)h1h, N);
    }
    gcn_node_kernel<<<N, 64>>>(b1);

    // GAT:  hgh fp16 = hA @ Wg
    {
        void* hA;  cudaGetSymbolAddress(&hA, g_hA);
        void* hgh; cudaGetSymbolAddress(&hgh, g_hgh);
        gemm_tf32_gat_kernel<<<dim3(mtiles, NHEADS), 256>>>(
            (const float*)hA, Wg, (__half*)hgh, N);
    }
    att_kernel<<<(N * 32 + 255) / 256, 256>>>(att_src, att_dst, N);
    gat_node_kernel<<<N, 64>>>(bg);

    // SAGE
    sage_node_kernel<<<N, 64>>>();
    {
        void* macc; cudaGetSymbolAddress(&macc, g_macc);
        void* hB;   cudaGetSymbolAddress(&hB, g_hB);
        gemm2_tf32_kernel<<<mtiles, 256>>>(
            (const float*)macc, Wl, (const float*)hB, Wr, bl, out_emb, N);
    }

    // heads
    heads_kernel<<<(N * 32 + 255) / 256, 256>>>(
        out_emb, a1w, a1b, a2w, a2b, r1w, r1b, r2w, r2b, out_an, out_rk, N);
}